// round 6
// baseline (speedup 1.0000x reference)
#include <cuda_runtime.h>
#include <cstddef>

#define D 128
#define D4 32            // float4 per row
#define MAXN 100000
#define MAXE 1600000

// Scratch (device globals -- no allocation allowed).
// float4-typed so every access is guaranteed 16B-aligned (RED.ADD.F32X4 / LDG.128).
__device__ float  g_dis[MAXN];
__device__ float4 g_hs [MAXN * D4];
__device__ float4 g_acc[MAXN * D4];
__device__ float4 g_x2 [MAXN * D4];

// ---------------- degree / norm ----------------
__global__ void k_deg_init(float* __restrict__ deg, int n) {
    int i = blockIdx.x * blockDim.x + threadIdx.x;
    if (i < n) deg[i] = 1.0f;  // self-loop
}

__global__ void k_deg(const int* __restrict__ dst, float* __restrict__ deg, int E) {
    int e = blockIdx.x * blockDim.x + threadIdx.x;
    if (e < E) atomicAdd(deg + dst[e], 1.0f);  // count on dst
}

__global__ void k_rsqrt(float* __restrict__ deg, int n) {
    int i = blockIdx.x * blockDim.x + threadIdx.x;
    if (i < n) deg[i] = rsqrtf(deg[i]);
}

// ---------------- GEMM: hs[m][:] = acc[m][:] = (A[m] @ W) * dis[m] ----------------
#define XS_LD 132  // 64x128 tile padded (132 floats = 33*16B, float4-safe)
#define GEMM_SMEM (64 * XS_LD * 4 + 128 * 128 * 4)

__global__ __launch_bounds__(256, 2) void k_gemm(
    const float* __restrict__ A, const float* __restrict__ W,
    const float* __restrict__ dis, float4* __restrict__ hs,
    float4* __restrict__ acc, int M) {
    extern __shared__ float smem[];
    float* Xs = smem;               // [64][132]
    float* Ws = smem + 64 * XS_LD;  // [128][128]
    int tid = threadIdx.x;
    int m0 = blockIdx.x * 64;

    // Load W (128x128 = 4096 float4, 16 per thread)
    {
        const float4* Wv = (const float4*)W;
        float4* Wsv = (float4*)Ws;
#pragma unroll
        for (int i = 0; i < 16; i++) Wsv[tid + i * 256] = Wv[tid + i * 256];
    }
    // Load X tile (64x128 = 2048 float4, 8 per thread)
    {
#pragma unroll
        for (int i = 0; i < 8; i++) {
            int idx = tid + i * 256;
            int r = idx >> 5;
            int c4 = idx & 31;
            int m = m0 + r;
            float4 v = make_float4(0.f, 0.f, 0.f, 0.f);
            if (m < M) v = ((const float4*)(A + (size_t)m * D))[c4];
            *(float4*)(Xs + r * XS_LD + c4 * 4) = v;
        }
    }
    __syncthreads();

    int tx = tid & 15;   // 16 threads over 128 cols (8 cols each)
    int ty = tid >> 4;   // 16 threads over 64 rows (4 rows each)
    float accv[4][8];
#pragma unroll
    for (int i = 0; i < 4; i++)
#pragma unroll
        for (int j = 0; j < 8; j++) accv[i][j] = 0.f;

#pragma unroll 8
    for (int k = 0; k < 128; k++) {
        float4 w0 = *(const float4*)(Ws + k * 128 + tx * 8);
        float4 w1 = *(const float4*)(Ws + k * 128 + tx * 8 + 4);
        float a[4];
#pragma unroll
        for (int i = 0; i < 4; i++) a[i] = Xs[(ty * 4 + i) * XS_LD + k];
#pragma unroll
        for (int i = 0; i < 4; i++) {
            accv[i][0] += a[i] * w0.x; accv[i][1] += a[i] * w0.y;
            accv[i][2] += a[i] * w0.z; accv[i][3] += a[i] * w0.w;
            accv[i][4] += a[i] * w1.x; accv[i][5] += a[i] * w1.y;
            accv[i][6] += a[i] * w1.z; accv[i][7] += a[i] * w1.w;
        }
    }

#pragma unroll
    for (int i = 0; i < 4; i++) {
        int m = m0 + ty * 4 + i;
        if (m < M) {
            float s = dis[m];
            float4 v0 = make_float4(accv[i][0] * s, accv[i][1] * s,
                                    accv[i][2] * s, accv[i][3] * s);
            float4 v1 = make_float4(accv[i][4] * s, accv[i][5] * s,
                                    accv[i][6] * s, accv[i][7] * s);
            size_t base = (size_t)m * D4 + tx * 2;
            hs[base] = v0;  hs[base + 1] = v1;
            acc[base] = v0; acc[base + 1] = v1;  // self-loop contribution
        }
    }
}

// ---------------- edge scatter: acc[dst] += hs[src] (vector L2 reduction) ----------------
__global__ void k_scatter(const int* __restrict__ src,
                          const int* __restrict__ dst,
                          const float4* __restrict__ hs,
                          float4* __restrict__ acc, int E) {
    int w = (blockIdx.x * blockDim.x + threadIdx.x) >> 5;  // one warp per edge
    if (w >= E) return;
    int lane = threadIdx.x & 31;
    int s = src[w];
    int d = dst[w];
    float4 v = hs[(size_t)s * D4 + lane];
    // Native float4 atomicAdd (sm_90+), return unused -> RED.ADD.F32X4
    atomicAdd(&acc[(size_t)d * D4 + lane], v);
}

// ---------------- finalize: out = relu(acc * dis[row] + b) ----------------
__global__ void k_finalize(const float4* __restrict__ acc,
                           const float* __restrict__ dis,
                           const float* __restrict__ b,
                           float4* __restrict__ out, int n4) {
    int i = blockIdx.x * blockDim.x + threadIdx.x;
    if (i >= n4) return;
    int row = i >> 5;   // 32 float4 per row
    int c4 = i & 31;
    float s = dis[row];
    float4 a = acc[i];
    float4 bb = ((const float4*)b)[c4];
    float4 r;
    r.x = fmaxf(a.x * s + bb.x, 0.f);
    r.y = fmaxf(a.y * s + bb.y, 0.f);
    r.z = fmaxf(a.z * s + bb.z, 0.f);
    r.w = fmaxf(a.w * s + bb.w, 0.f);
    out[i] = r;
}

extern "C" void kernel_launch(void* const* d_in, const int* in_sizes, int n_in,
                              void* d_out, int out_size) {
    const float* x   = (const float*)d_in[0];
    const int*   ei  = (const int*)d_in[1];   // int64 in reference -> delivered as int32
    const float* W1  = (const float*)d_in[2];
    const float* b1  = (const float*)d_in[3];
    const float* W2  = (const float*)d_in[4];
    const float* b2  = (const float*)d_in[5];
    float4* out = (float4*)d_out;

    int N = in_sizes[0] / D;
    int E = in_sizes[1] / 2;
    const int* src = ei;
    const int* dst = ei + E;

    float *dis;
    float4 *hs, *acc, *x2;
    cudaGetSymbolAddress((void**)&dis, g_dis);
    cudaGetSymbolAddress((void**)&hs, g_hs);
    cudaGetSymbolAddress((void**)&acc, g_acc);
    cudaGetSymbolAddress((void**)&x2, g_x2);

    cudaFuncSetAttribute(k_gemm, cudaFuncAttributeMaxDynamicSharedMemorySize, GEMM_SMEM);

    int nb = (N + 255) / 256;
    int eb = (E + 255) / 256;
    int gblocks = (N + 63) / 64;
    long long warps = (long long)E * 32;
    int sblocks = (int)((warps + 255) / 256);
    int n4 = N * D4;
    int fblocks = (n4 + 255) / 256;

    // normalization factors
    k_deg_init<<<nb, 256>>>(dis, N);
    k_deg<<<eb, 256>>>(dst, dis, E);
    k_rsqrt<<<nb, 256>>>(dis, N);

    // layer 1
    k_gemm<<<gblocks, 256, GEMM_SMEM>>>(x, W1, dis, hs, acc, N);
    k_scatter<<<sblocks, 256>>>(src, dst, hs, acc, E);
    k_finalize<<<fblocks, 256>>>(acc, dis, b1, x2, n4);

    // layer 2
    k_gemm<<<gblocks, 256, GEMM_SMEM>>>((const float*)x2, W2, dis, hs, acc, N);
    k_scatter<<<sblocks, 256>>>(src, dst, hs, acc, E);
    k_finalize<<<fblocks, 256>>>(acc, dis, b2, out, n4);
}

// round 8
// speedup vs baseline: 1.0810x; 1.0810x over previous
#include <cuda_runtime.h>
#include <cstddef>

#define D 128
#define D4 32            // float4 per row
#define MAXN 100000
#define MAXE 1600000

// Scratch (device globals -- no allocation allowed).
// float4-typed so every access is guaranteed 16B-aligned (RED.ADD.F32X4 / LDG.128).
__device__ float  g_dis[MAXN];
__device__ float4 g_hs [MAXN * D4];
__device__ float4 g_acc[MAXN * D4];

// ---------------- degree / norm ----------------
__global__ void k_deg_init(float* __restrict__ deg, int n) {
    int i = blockIdx.x * blockDim.x + threadIdx.x;
    if (i < n) deg[i] = 1.0f;  // self-loop
}

__global__ void k_deg(const int* __restrict__ dst, float* __restrict__ deg, int E) {
    int e = blockIdx.x * blockDim.x + threadIdx.x;
    if (e < E) atomicAdd(deg + dst[e], 1.0f);  // count on dst
}

__global__ void k_rsqrt(float* __restrict__ deg, int n) {
    int i = blockIdx.x * blockDim.x + threadIdx.x;
    if (i < n) deg[i] = rsqrtf(deg[i]);
}

// ---------------- GEMM: hs[m] = acc_out[m] = (X[m] @ W) * dis[m] ----------------
// X input is either A (raw features, layer 1) or the fused activation of the
// previous layer's accumulator: relu(dis[m]*ACC[m] + bias)  (layer 2).
// 64x128 tile, 128 threads, 8x8 microkernel -> 64B smem per 64 FMA (1.0 B/FMA).
#define XLD 132   // 64-row X tile, padded row (33 float4) to dodge conflicts
#define GEMM_SMEM (64 * XLD * 4 + 128 * 128 * 4)   // 33792 + 65536 = 99328 B

__global__ __launch_bounds__(128, 2) void k_gemm(
    const float* __restrict__ A,        // layer-1 input (or null)
    const float4* __restrict__ ACC,     // layer-2 fused input (or null)
    const float* __restrict__ W,
    const float* __restrict__ dis,
    const float* __restrict__ bias,     // bias for fused activation path
    float4* __restrict__ hs,
    float4* __restrict__ acc_out, int M) {
    extern __shared__ float smem[];
    float* Xs = smem;                 // [64][XLD]
    float* Ws = smem + 64 * XLD;      // [128][128]
    const int tid = threadIdx.x;
    const int m0 = blockIdx.x * 64;

    // Load W (4096 float4, 32 per thread)
    {
        const float4* Wv = (const float4*)W;
        float4* Wsv = (float4*)Ws;
#pragma unroll
        for (int i = 0; i < 32; i++) Wsv[tid + i * 128] = Wv[tid + i * 128];
    }
    // Load X tile (64 rows x 32 float4 = 2048 float4, 16 per thread)
    if (A != nullptr) {
#pragma unroll
        for (int i = 0; i < 16; i++) {
            int idx = tid + i * 128;
            int r = idx >> 5, c4 = idx & 31;
            int m = m0 + r;
            float4 v = make_float4(0.f, 0.f, 0.f, 0.f);
            if (m < M) v = ((const float4*)(A + (size_t)m * D))[c4];
            *(float4*)(Xs + r * XLD + c4 * 4) = v;
        }
    } else {  // fused: x = relu(dis[m]*ACC[m] + bias)
#pragma unroll
        for (int i = 0; i < 16; i++) {
            int idx = tid + i * 128;
            int r = idx >> 5, c4 = idx & 31;
            int m = m0 + r;
            float4 v = make_float4(0.f, 0.f, 0.f, 0.f);
            if (m < M) {
                float s = dis[m];
                float4 a = ACC[(size_t)m * D4 + c4];
                float4 bb = ((const float4*)bias)[c4];
                v.x = fmaxf(a.x * s + bb.x, 0.f);
                v.y = fmaxf(a.y * s + bb.y, 0.f);
                v.z = fmaxf(a.z * s + bb.z, 0.f);
                v.w = fmaxf(a.w * s + bb.w, 0.f);
            }
            *(float4*)(Xs + r * XLD + c4 * 4) = v;
        }
    }
    __syncthreads();

    const int tx = tid & 15;   // 16 col-groups of 8 cols
    const int ty = tid >> 4;   // 8 row-groups of 8 rows
    float accv[8][8];
#pragma unroll
    for (int i = 0; i < 8; i++)
#pragma unroll
        for (int j = 0; j < 8; j++) accv[i][j] = 0.f;

    const float4* Ws4 = (const float4*)Ws;
#pragma unroll 4
    for (int k = 0; k < 128; k++) {
        float4 w0 = Ws4[k * 32 + tx * 2];
        float4 w1 = Ws4[k * 32 + tx * 2 + 1];
        float a[8];
#pragma unroll
        for (int i = 0; i < 8; i++) a[i] = Xs[(ty * 8 + i) * XLD + k];  // broadcast
#pragma unroll
        for (int i = 0; i < 8; i++) {
            accv[i][0] += a[i] * w0.x; accv[i][1] += a[i] * w0.y;
            accv[i][2] += a[i] * w0.z; accv[i][3] += a[i] * w0.w;
            accv[i][4] += a[i] * w1.x; accv[i][5] += a[i] * w1.y;
            accv[i][6] += a[i] * w1.z; accv[i][7] += a[i] * w1.w;
        }
    }

#pragma unroll
    for (int i = 0; i < 8; i++) {
        int m = m0 + ty * 8 + i;
        if (m < M) {
            float s = dis[m];
            float4 v0 = make_float4(accv[i][0] * s, accv[i][1] * s,
                                    accv[i][2] * s, accv[i][3] * s);
            float4 v1 = make_float4(accv[i][4] * s, accv[i][5] * s,
                                    accv[i][6] * s, accv[i][7] * s);
            size_t base = (size_t)m * D4 + tx * 2;
            hs[base] = v0;      hs[base + 1] = v1;
            acc_out[base] = v0; acc_out[base + 1] = v1;  // self-loop contribution
        }
    }
}

// ---------------- edge scatter: acc[dst] += hs[src] (vector L2 reduction) ----------------
__global__ void k_scatter(const int* __restrict__ src,
                          const int* __restrict__ dst,
                          const float4* __restrict__ hs,
                          float4* __restrict__ acc, int E) {
    int w = (blockIdx.x * blockDim.x + threadIdx.x) >> 5;  // one warp per edge
    if (w >= E) return;
    int lane = threadIdx.x & 31;
    int s = src[w];
    int d = dst[w];
    float4 v = hs[(size_t)s * D4 + lane];
    atomicAdd(&acc[(size_t)d * D4 + lane], v);  // RED.ADD.F32X4, no return
}

// ---------------- finalize (output layer only): out = relu(acc*dis[row] + b) ----------------
__global__ void k_finalize(const float4* __restrict__ acc,
                           const float* __restrict__ dis,
                           const float* __restrict__ b,
                           float4* __restrict__ out, int n4) {
    int i = blockIdx.x * blockDim.x + threadIdx.x;
    if (i >= n4) return;
    int row = i >> 5;
    int c4 = i & 31;
    float s = dis[row];
    float4 a = acc[i];
    float4 bb = ((const float4*)b)[c4];
    float4 r;
    r.x = fmaxf(a.x * s + bb.x, 0.f);
    r.y = fmaxf(a.y * s + bb.y, 0.f);
    r.z = fmaxf(a.z * s + bb.z, 0.f);
    r.w = fmaxf(a.w * s + bb.w, 0.f);
    out[i] = r;
}

extern "C" void kernel_launch(void* const* d_in, const int* in_sizes, int n_in,
                              void* d_out, int out_size) {
    const float* x   = (const float*)d_in[0];
    const int*   ei  = (const int*)d_in[1];   // int64 in reference -> delivered as int32
    const float* W1  = (const float*)d_in[2];
    const float* b1  = (const float*)d_in[3];
    const float* W2  = (const float*)d_in[4];
    const float* b2  = (const float*)d_in[5];
    float4* out = (float4*)d_out;

    int N = in_sizes[0] / D;
    int E = in_sizes[1] / 2;
    const int* src = ei;
    const int* dst = ei + E;

    float *dis;
    float4 *hs, *acc;
    cudaGetSymbolAddress((void**)&dis, g_dis);
    cudaGetSymbolAddress((void**)&hs, g_hs);
    cudaGetSymbolAddress((void**)&acc, g_acc);

    cudaFuncSetAttribute(k_gemm, cudaFuncAttributeMaxDynamicSharedMemorySize, GEMM_SMEM);

    int nb = (N + 255) / 256;
    int eb = (E + 255) / 256;
    int gblocks = (N + 63) / 64;
    long long warps = (long long)E * 32;
    int sblocks = (int)((warps + 255) / 256);
    int n4 = N * D4;
    int fblocks = (n4 + 255) / 256;

    // normalization factors
    k_deg_init<<<nb, 256>>>(dis, N);
    k_deg<<<eb, 256>>>(dst, dis, E);
    k_rsqrt<<<nb, 256>>>(dis, N);

    // layer 1
    k_gemm<<<gblocks, 128, GEMM_SMEM>>>(x, nullptr, W1, dis, nullptr, hs, acc, N);
    k_scatter<<<sblocks, 256>>>(src, dst, hs, acc, E);

    // layer 2 (input fused: relu(dis*acc + b1) computed during tile load)
    k_gemm<<<gblocks, 128, GEMM_SMEM>>>(nullptr, acc, W2, dis, b1, hs, acc, N);
    k_scatter<<<sblocks, 256>>>(src, dst, hs, acc, E);
    k_finalize<<<fblocks, 256>>>(acc, dis, b2, out, n4);
}

// round 9
// speedup vs baseline: 1.2671x; 1.1722x over previous
#include <cuda_runtime.h>
#include <cstddef>

#define D 128
#define D4 32            // float4 per row
#define MAXN 100000
#define MAXE 1600000

// Scratch (device globals -- no allocation allowed).
__device__ float  g_dis[MAXN];
__device__ float4 g_hs [MAXN * D4];
__device__ float4 g_acc[MAXN * D4];
__device__ int    g_cnt[MAXN];
__device__ int    g_row[MAXN + 1];
__device__ int    g_cur[MAXN];
__device__ int    g_esrc[MAXE];

// ---------------- bucket build: histogram -> scan -> fill ----------------
__global__ void k_zero(int* __restrict__ cnt, int n) {
    int i = blockIdx.x * blockDim.x + threadIdx.x;
    if (i < n) cnt[i] = 0;
}

__global__ void k_hist(const int* __restrict__ dst, int* __restrict__ cnt, int E) {
    int e = blockIdx.x * blockDim.x + threadIdx.x;
    if (e < E) atomicAdd(cnt + dst[e], 1);
}

#define SCAN_T 1024
__global__ void k_scan(const int* __restrict__ cnt, int* __restrict__ row_start,
                       int* __restrict__ cursor, float* __restrict__ dis, int n) {
    __shared__ int part[SCAN_T];
    int tid = threadIdx.x;
    int chunk = (n + SCAN_T - 1) / SCAN_T;
    int lo = tid * chunk;
    int hi = min(lo + chunk, n);
    int s = 0;
    for (int i = lo; i < hi; i++) s += cnt[i];
    part[tid] = s;
    __syncthreads();
    // Hillis-Steele inclusive scan over 1024 partials
    for (int off = 1; off < SCAN_T; off <<= 1) {
        int t = 0;
        if (tid >= off) t = part[tid - off];
        __syncthreads();
        if (tid >= off) part[tid] += t;
        __syncthreads();
    }
    int run = part[tid] - s;  // exclusive
    for (int i = lo; i < hi; i++) {
        int c = cnt[i];
        row_start[i] = run;
        cursor[i] = run;
        dis[i] = rsqrtf((float)(c + 1));  // degree incl. self-loop
        run += c;
    }
    if (tid == SCAN_T - 1) row_start[n] = run;
}

__global__ void k_bucket(const int* __restrict__ src, const int* __restrict__ dst,
                         int* __restrict__ cursor, int* __restrict__ esrc, int E) {
    int e = blockIdx.x * blockDim.x + threadIdx.x;
    if (e >= E) return;
    int pos = atomicAdd(cursor + dst[e], 1);
    esrc[pos] = src[e];
}

// ---------------- GEMM: hs[m] = (X[m] @ W) * dis[m] ----------------
#define XLD 132
#define GEMM_SMEM (64 * XLD * 4 + 128 * 128 * 4)

__global__ __launch_bounds__(128, 2) void k_gemm(
    const float* __restrict__ A,        // layer-1 input (or null)
    const float4* __restrict__ ACC,     // layer-2 fused input (or null)
    const float* __restrict__ W,
    const float* __restrict__ dis,
    const float* __restrict__ bias,
    float4* __restrict__ hs, int M) {
    extern __shared__ float smem[];
    float* Xs = smem;                 // [64][XLD]
    float* Ws = smem + 64 * XLD;      // [128][128]
    const int tid = threadIdx.x;
    const int m0 = blockIdx.x * 64;

    {
        const float4* Wv = (const float4*)W;
        float4* Wsv = (float4*)Ws;
#pragma unroll
        for (int i = 0; i < 32; i++) Wsv[tid + i * 128] = Wv[tid + i * 128];
    }
    if (A != nullptr) {
#pragma unroll
        for (int i = 0; i < 16; i++) {
            int idx = tid + i * 128;
            int r = idx >> 5, c4 = idx & 31;
            int m = m0 + r;
            float4 v = make_float4(0.f, 0.f, 0.f, 0.f);
            if (m < M) v = ((const float4*)(A + (size_t)m * D))[c4];
            *(float4*)(Xs + r * XLD + c4 * 4) = v;
        }
    } else {  // fused: x = relu(dis[m]*ACC[m] + bias)
#pragma unroll
        for (int i = 0; i < 16; i++) {
            int idx = tid + i * 128;
            int r = idx >> 5, c4 = idx & 31;
            int m = m0 + r;
            float4 v = make_float4(0.f, 0.f, 0.f, 0.f);
            if (m < M) {
                float s = dis[m];
                float4 a = ACC[(size_t)m * D4 + c4];
                float4 bb = ((const float4*)bias)[c4];
                v.x = fmaxf(a.x * s + bb.x, 0.f);
                v.y = fmaxf(a.y * s + bb.y, 0.f);
                v.z = fmaxf(a.z * s + bb.z, 0.f);
                v.w = fmaxf(a.w * s + bb.w, 0.f);
            }
            *(float4*)(Xs + r * XLD + c4 * 4) = v;
        }
    }
    __syncthreads();

    const int tx = tid & 15;
    const int ty = tid >> 4;
    float accv[8][8];
#pragma unroll
    for (int i = 0; i < 8; i++)
#pragma unroll
        for (int j = 0; j < 8; j++) accv[i][j] = 0.f;

    const float4* Ws4 = (const float4*)Ws;
#pragma unroll 4
    for (int k = 0; k < 128; k++) {
        float4 w0 = Ws4[k * 32 + tx * 2];
        float4 w1 = Ws4[k * 32 + tx * 2 + 1];
        float a[8];
#pragma unroll
        for (int i = 0; i < 8; i++) a[i] = Xs[(ty * 8 + i) * XLD + k];
#pragma unroll
        for (int i = 0; i < 8; i++) {
            accv[i][0] += a[i] * w0.x; accv[i][1] += a[i] * w0.y;
            accv[i][2] += a[i] * w0.z; accv[i][3] += a[i] * w0.w;
            accv[i][4] += a[i] * w1.x; accv[i][5] += a[i] * w1.y;
            accv[i][6] += a[i] * w1.z; accv[i][7] += a[i] * w1.w;
        }
    }

#pragma unroll
    for (int i = 0; i < 8; i++) {
        int m = m0 + ty * 8 + i;
        if (m < M) {
            float s = dis[m];
            float4 v0 = make_float4(accv[i][0] * s, accv[i][1] * s,
                                    accv[i][2] * s, accv[i][3] * s);
            float4 v1 = make_float4(accv[i][4] * s, accv[i][5] * s,
                                    accv[i][6] * s, accv[i][7] * s);
            size_t base = (size_t)m * D4 + tx * 2;
            hs[base] = v0; hs[base + 1] = v1;
        }
    }
}

// ---------------- gather-reduce: out[n] = hs[n] + sum_{e in bucket(n)} hs[esrc[e]] ----------------
// One warp per node; row accumulated in registers, written once.
// FUSE=1: apply relu(dis*a + bias) (final layer output).
template <int FUSE>
__global__ void k_gather(const float4* __restrict__ hs,
                         const int* __restrict__ esrc,
                         const int* __restrict__ row_start,
                         const float* __restrict__ dis,
                         const float* __restrict__ bias,
                         float4* __restrict__ outp, int n) {
    int w = (blockIdx.x * blockDim.x + threadIdx.x) >> 5;
    if (w >= n) return;
    int lane = threadIdx.x & 31;
    float4 a = hs[(size_t)w * D4 + lane];  // self-loop
    int i = row_start[w];
    int hi = row_start[w + 1];
    for (; i + 4 <= hi; i += 4) {
        int s0 = __ldg(esrc + i), s1 = __ldg(esrc + i + 1);
        int s2 = __ldg(esrc + i + 2), s3 = __ldg(esrc + i + 3);
        float4 v0 = hs[(size_t)s0 * D4 + lane];
        float4 v1 = hs[(size_t)s1 * D4 + lane];
        float4 v2 = hs[(size_t)s2 * D4 + lane];
        float4 v3 = hs[(size_t)s3 * D4 + lane];
        a.x += v0.x + v1.x + v2.x + v3.x;
        a.y += v0.y + v1.y + v2.y + v3.y;
        a.z += v0.z + v1.z + v2.z + v3.z;
        a.w += v0.w + v1.w + v2.w + v3.w;
    }
    for (; i < hi; i++) {
        int s = __ldg(esrc + i);
        float4 v = hs[(size_t)s * D4 + lane];
        a.x += v.x; a.y += v.y; a.z += v.z; a.w += v.w;
    }
    if (FUSE) {
        float sc = dis[w];
        float4 bb = ((const float4*)bias)[lane];
        a.x = fmaxf(a.x * sc + bb.x, 0.f);
        a.y = fmaxf(a.y * sc + bb.y, 0.f);
        a.z = fmaxf(a.z * sc + bb.z, 0.f);
        a.w = fmaxf(a.w * sc + bb.w, 0.f);
    }
    outp[(size_t)w * D4 + lane] = a;
}

extern "C" void kernel_launch(void* const* d_in, const int* in_sizes, int n_in,
                              void* d_out, int out_size) {
    const float* x   = (const float*)d_in[0];
    const int*   ei  = (const int*)d_in[1];   // int64 in reference -> delivered as int32
    const float* W1  = (const float*)d_in[2];
    const float* b1  = (const float*)d_in[3];
    const float* W2  = (const float*)d_in[4];
    const float* b2  = (const float*)d_in[5];
    float4* out = (float4*)d_out;

    int N = in_sizes[0] / D;
    int E = in_sizes[1] / 2;
    const int* src = ei;
    const int* dst = ei + E;

    float *dis;
    float4 *hs, *acc;
    int *cnt, *row, *cur, *esrc;
    cudaGetSymbolAddress((void**)&dis, g_dis);
    cudaGetSymbolAddress((void**)&hs, g_hs);
    cudaGetSymbolAddress((void**)&acc, g_acc);
    cudaGetSymbolAddress((void**)&cnt, g_cnt);
    cudaGetSymbolAddress((void**)&row, g_row);
    cudaGetSymbolAddress((void**)&cur, g_cur);
    cudaGetSymbolAddress((void**)&esrc, g_esrc);

    cudaFuncSetAttribute(k_gemm, cudaFuncAttributeMaxDynamicSharedMemorySize, GEMM_SMEM);

    int nb = (N + 255) / 256;
    int eb = (E + 255) / 256;
    int gblocks = (N + 63) / 64;
    long long gw = (long long)N * 32;
    int gab = (int)((gw + 255) / 256);

    // bucket build (also produces dis)
    k_zero<<<nb, 256>>>(cnt, N);
    k_hist<<<eb, 256>>>(dst, cnt, E);
    k_scan<<<1, SCAN_T>>>(cnt, row, cur, dis, N);
    k_bucket<<<eb, 256>>>(src, dst, cur, esrc, E);

    // layer 1
    k_gemm<<<gblocks, 128, GEMM_SMEM>>>(x, nullptr, W1, dis, nullptr, hs, N);
    k_gather<0><<<gab, 256>>>(hs, esrc, row, dis, nullptr, acc, N);

    // layer 2 (GEMM input fused: relu(dis*acc + b1); gather output fused: relu(dis*a + b2))
    k_gemm<<<gblocks, 128, GEMM_SMEM>>>(nullptr, acc, W2, dis, b1, hs, N);
    k_gather<1><<<gab, 256>>>(hs, esrc, row, dis, b2, out, N);
}

// round 10
// speedup vs baseline: 1.3453x; 1.0617x over previous
#include <cuda_runtime.h>
#include <cstddef>

#define D 128
#define D4 32            // float4 per row
#define MAXN 100000
#define MAXE 1600000

// Scratch (device globals -- no allocation allowed).
__device__ float  g_dis[MAXN];
__device__ float4 g_hs [MAXN * D4];
__device__ float4 g_acc[MAXN * D4];
__device__ int    g_cnt[MAXN];
__device__ int    g_row[MAXN + 1];
__device__ int    g_cur[MAXN];
__device__ int    g_esrc[MAXE];

// ---------------- bucket build: histogram -> scan -> fill ----------------
__global__ void k_zero(int* __restrict__ cnt, int n) {
    int i = blockIdx.x * blockDim.x + threadIdx.x;
    if (i < n) cnt[i] = 0;
}

__global__ void k_hist(const int* __restrict__ dst, int* __restrict__ cnt, int E) {
    int e = blockIdx.x * blockDim.x + threadIdx.x;
    if (e < E) atomicAdd(cnt + dst[e], 1);
}

#define SCAN_T 1024
__global__ void k_scan(const int* __restrict__ cnt, int* __restrict__ row_start,
                       int* __restrict__ cursor, float* __restrict__ dis, int n) {
    __shared__ int part[SCAN_T];
    int tid = threadIdx.x;
    int chunk = (n + SCAN_T - 1) / SCAN_T;
    int lo = tid * chunk;
    int hi = min(lo + chunk, n);
    int s = 0;
    for (int i = lo; i < hi; i++) s += cnt[i];
    part[tid] = s;
    __syncthreads();
    for (int off = 1; off < SCAN_T; off <<= 1) {
        int t = 0;
        if (tid >= off) t = part[tid - off];
        __syncthreads();
        if (tid >= off) part[tid] += t;
        __syncthreads();
    }
    int run = part[tid] - s;  // exclusive
    for (int i = lo; i < hi; i++) {
        int c = cnt[i];
        row_start[i] = run;
        cursor[i] = run;
        dis[i] = rsqrtf((float)(c + 1));  // degree incl. self-loop
        run += c;
    }
    if (tid == SCAN_T - 1) row_start[n] = run;
}

__global__ void k_bucket(const int* __restrict__ src, const int* __restrict__ dst,
                         int* __restrict__ cursor, int* __restrict__ esrc, int E) {
    int e = blockIdx.x * blockDim.x + threadIdx.x;
    if (e >= E) return;
    int pos = atomicAdd(cursor + dst[e], 1);
    esrc[pos] = src[e];
}

// ---------------- tf32 tensor-core GEMM: hs[m] = (X[m] @ W) * dis[m] ----------------
// 64x128 tile, 128 threads (4 warps, 16 rows each), mma.sync.m16n8k8.tf32.
// X and W pre-converted to tf32 at smem-fill; W stored in fragment order so the
// inner-loop B load is one conflict-free ld.shared.u64 per mma.
#define XLD 132   // padded row: bank = (4*row + col) % 32 -> A-frag loads conflict-free
#define GEMM_SMEM (64 * XLD * 4 + 128 * 128 * 4)   // 33792 + 65536 = 99328 B

__device__ __forceinline__ unsigned cvt_tf32(float f) {
    unsigned u;
    asm("cvt.rna.tf32.f32 %0, %1;" : "=r"(u) : "f"(f));
    return u;
}

__global__ __launch_bounds__(128, 2) void k_gemm(
    const float* __restrict__ A,        // layer-1 input (or null)
    const float4* __restrict__ ACC,     // layer-2 fused input (or null)
    const float* __restrict__ W,
    const float* __restrict__ dis,
    const float* __restrict__ bias,
    float4* __restrict__ hs, int M) {
    extern __shared__ unsigned smem_u[];
    unsigned* Xs = smem_u;                     // [64][XLD] tf32 bits
    unsigned* Wf = smem_u + 64 * XLD;          // frag layout: [kt][nt][lane][slot]
    const int tid = threadIdx.x;
    const int warp = tid >> 5;
    const int lane = tid & 31;
    const int gid = lane >> 2;   // 0..7
    const int tig = lane & 3;    // 0..3
    const int m0 = blockIdx.x * 64;

    // Load + convert W into fragment-order smem.
    // frag addr for W[k][n]: kt=k/8, nt=n/8, t=(n%8)*4+(k%4), slot=(k%8)/4
    {
        const float4* Wv = (const float4*)W;
#pragma unroll
        for (int i = 0; i < 32; i++) {
            int idx = tid + i * 128;          // 4096 float4
            int k = idx >> 5, n4 = idx & 31;
            float4 w = Wv[idx];
            int kt = k >> 3, kin = k & 7;
            int slot = kin >> 2, kk = kin & 3;
            float v[4] = {w.x, w.y, w.z, w.w};
#pragma unroll
            for (int j = 0; j < 4; j++) {
                int n = n4 * 4 + j;
                int nt = n >> 3, t = (n & 7) * 4 + kk;
                Wf[(((kt * 16) + nt) * 32 + t) * 2 + slot] = cvt_tf32(v[j]);
            }
        }
    }
    // Load + convert X tile (64 rows x 32 float4)
    if (A != nullptr) {
#pragma unroll
        for (int i = 0; i < 16; i++) {
            int idx = tid + i * 128;
            int r = idx >> 5, c4 = idx & 31;
            int m = m0 + r;
            float4 v = make_float4(0.f, 0.f, 0.f, 0.f);
            if (m < M) v = ((const float4*)(A + (size_t)m * D))[c4];
            uint4 u = make_uint4(cvt_tf32(v.x), cvt_tf32(v.y), cvt_tf32(v.z), cvt_tf32(v.w));
            *(uint4*)(Xs + r * XLD + c4 * 4) = u;
        }
    } else {  // fused: x = relu(dis[m]*ACC[m] + bias)
#pragma unroll
        for (int i = 0; i < 16; i++) {
            int idx = tid + i * 128;
            int r = idx >> 5, c4 = idx & 31;
            int m = m0 + r;
            float4 v = make_float4(0.f, 0.f, 0.f, 0.f);
            if (m < M) {
                float s = dis[m];
                float4 a = ACC[(size_t)m * D4 + c4];
                float4 bb = ((const float4*)bias)[c4];
                v.x = fmaxf(a.x * s + bb.x, 0.f);
                v.y = fmaxf(a.y * s + bb.y, 0.f);
                v.z = fmaxf(a.z * s + bb.z, 0.f);
                v.w = fmaxf(a.w * s + bb.w, 0.f);
            }
            uint4 u = make_uint4(cvt_tf32(v.x), cvt_tf32(v.y), cvt_tf32(v.z), cvt_tf32(v.w));
            *(uint4*)(Xs + r * XLD + c4 * 4) = u;
        }
    }
    __syncthreads();

    const int mrow = warp * 16;             // this warp's rows within tile
    float d[16][4];
#pragma unroll
    for (int nt = 0; nt < 16; nt++)
#pragma unroll
        for (int j = 0; j < 4; j++) d[nt][j] = 0.f;

#pragma unroll
    for (int kt = 0; kt < 16; kt++) {
        // A fragment (m16n8k8 tf32, row-major):
        // a0=(gid,tig) a1=(gid+8,tig) a2=(gid,tig+4) a3=(gid+8,tig+4)
        unsigned a0 = Xs[(mrow + gid) * XLD + kt * 8 + tig];
        unsigned a1 = Xs[(mrow + gid + 8) * XLD + kt * 8 + tig];
        unsigned a2 = Xs[(mrow + gid) * XLD + kt * 8 + tig + 4];
        unsigned a3 = Xs[(mrow + gid + 8) * XLD + kt * 8 + tig + 4];
#pragma unroll
        for (int nt = 0; nt < 16; nt++) {
            uint2 b = *(const uint2*)(Wf + (((kt * 16) + nt) * 32 + lane) * 2);
            asm volatile(
                "mma.sync.aligned.m16n8k8.row.col.f32.tf32.tf32.f32 "
                "{%0,%1,%2,%3}, {%4,%5,%6,%7}, {%8,%9}, {%0,%1,%2,%3};"
                : "+f"(d[nt][0]), "+f"(d[nt][1]), "+f"(d[nt][2]), "+f"(d[nt][3])
                : "r"(a0), "r"(a1), "r"(a2), "r"(a3), "r"(b.x), "r"(b.y));
        }
    }

    // Epilogue: c0=(gid,2tig) c1=(gid,2tig+1) c2=(gid+8,2tig) c3=(gid+8,2tig+1)
    int mA = m0 + mrow + gid;
    int mB = mA + 8;
    float sA = (mA < M) ? dis[mA] : 0.f;
    float sB = (mB < M) ? dis[mB] : 0.f;
    float2* h2 = (float2*)hs;
#pragma unroll
    for (int nt = 0; nt < 16; nt++) {
        int col2 = nt * 4 + tig;   // float2 index within row (64 float2 per row)
        if (mA < M) h2[(size_t)mA * 64 + col2] = make_float2(d[nt][0] * sA, d[nt][1] * sA);
        if (mB < M) h2[(size_t)mB * 64 + col2] = make_float2(d[nt][2] * sB, d[nt][3] * sB);
    }
}

// ---------------- gather-reduce: out[n] = hs[n] + sum_{e in bucket(n)} hs[esrc[e]] ----------------
template <int FUSE>
__global__ void k_gather(const float4* __restrict__ hs,
                         const int* __restrict__ esrc,
                         const int* __restrict__ row_start,
                         const float* __restrict__ dis,
                         const float* __restrict__ bias,
                         float4* __restrict__ outp, int n) {
    int w = (blockIdx.x * blockDim.x + threadIdx.x) >> 5;
    if (w >= n) return;
    int lane = threadIdx.x & 31;
    float4 a = hs[(size_t)w * D4 + lane];  // self-loop
    int i = row_start[w];
    int hi = row_start[w + 1];
    for (; i + 4 <= hi; i += 4) {
        int s0 = __ldg(esrc + i), s1 = __ldg(esrc + i + 1);
        int s2 = __ldg(esrc + i + 2), s3 = __ldg(esrc + i + 3);
        float4 v0 = hs[(size_t)s0 * D4 + lane];
        float4 v1 = hs[(size_t)s1 * D4 + lane];
        float4 v2 = hs[(size_t)s2 * D4 + lane];
        float4 v3 = hs[(size_t)s3 * D4 + lane];
        a.x += v0.x + v1.x + v2.x + v3.x;
        a.y += v0.y + v1.y + v2.y + v3.y;
        a.z += v0.z + v1.z + v2.z + v3.z;
        a.w += v0.w + v1.w + v2.w + v3.w;
    }
    for (; i < hi; i++) {
        int s = __ldg(esrc + i);
        float4 v = hs[(size_t)s * D4 + lane];
        a.x += v.x; a.y += v.y; a.z += v.z; a.w += v.w;
    }
    if (FUSE) {
        float sc = dis[w];
        float4 bb = ((const float4*)bias)[lane];
        a.x = fmaxf(a.x * sc + bb.x, 0.f);
        a.y = fmaxf(a.y * sc + bb.y, 0.f);
        a.z = fmaxf(a.z * sc + bb.z, 0.f);
        a.w = fmaxf(a.w * sc + bb.w, 0.f);
    }
    outp[(size_t)w * D4 + lane] = a;
}

extern "C" void kernel_launch(void* const* d_in, const int* in_sizes, int n_in,
                              void* d_out, int out_size) {
    const float* x   = (const float*)d_in[0];
    const int*   ei  = (const int*)d_in[1];   // int64 in reference -> delivered as int32
    const float* W1  = (const float*)d_in[2];
    const float* b1  = (const float*)d_in[3];
    const float* W2  = (const float*)d_in[4];
    const float* b2  = (const float*)d_in[5];
    float4* out = (float4*)d_out;

    int N = in_sizes[0] / D;
    int E = in_sizes[1] / 2;
    const int* src = ei;
    const int* dst = ei + E;

    float *dis;
    float4 *hs, *acc;
    int *cnt, *row, *cur, *esrc;
    cudaGetSymbolAddress((void**)&dis, g_dis);
    cudaGetSymbolAddress((void**)&hs, g_hs);
    cudaGetSymbolAddress((void**)&acc, g_acc);
    cudaGetSymbolAddress((void**)&cnt, g_cnt);
    cudaGetSymbolAddress((void**)&row, g_row);
    cudaGetSymbolAddress((void**)&cur, g_cur);
    cudaGetSymbolAddress((void**)&esrc, g_esrc);

    cudaFuncSetAttribute(k_gemm, cudaFuncAttributeMaxDynamicSharedMemorySize, GEMM_SMEM);

    int nb = (N + 255) / 256;
    int eb = (E + 255) / 256;
    int gblocks = (N + 63) / 64;
    long long gw = (long long)N * 32;
    int gab = (int)((gw + 255) / 256);

    // bucket build (also produces dis)
    k_zero<<<nb, 256>>>(cnt, N);
    k_hist<<<eb, 256>>>(dst, cnt, E);
    k_scan<<<1, SCAN_T>>>(cnt, row, cur, dis, N);
    k_bucket<<<eb, 256>>>(src, dst, cur, esrc, E);

    // layer 1
    k_gemm<<<gblocks, 128, GEMM_SMEM>>>(x, nullptr, W1, dis, nullptr, hs, N);
    k_gather<0><<<gab, 256>>>(hs, esrc, row, dis, nullptr, acc, N);

    // layer 2 (GEMM input fused: relu(dis*acc + b1); gather output fused: relu(dis*a + b2))
    k_gemm<<<gblocks, 128, GEMM_SMEM>>>(nullptr, acc, W2, dis, b1, hs, N);
    k_gather<1><<<gab, 256>>>(hs, esrc, row, dis, b2, out, N);
}

// round 12
// speedup vs baseline: 1.6943x; 1.2594x over previous
#include <cuda_runtime.h>
#include <cuda_fp16.h>
#include <cstddef>

#define D 128
#define D4 32            // float4 per row
#define MAXN 100000
#define MAXE 1600000

// Scratch (device globals -- no allocation allowed).
__device__ float   g_dis[MAXN];
__device__ __half2 g_hsh[MAXN * 64];     // hs rows in fp16 (64 half2 = 128 cols)
__device__ float4  g_acc[MAXN * D4];
__device__ int     g_cnt[MAXN];
__device__ int     g_row[MAXN + 1];
__device__ int     g_cur[MAXN];
__device__ int     g_esrc[MAXE];
__device__ unsigned g_wf1[128 * 128];    // W1 in tf32 fragment order
__device__ unsigned g_wf2[128 * 128];    // W2 in tf32 fragment order

// ---------------- bucket build: histogram -> scan -> fill ----------------
__global__ void k_zero(int* __restrict__ cnt, int n) {
    int i = blockIdx.x * blockDim.x + threadIdx.x;
    if (i < n) cnt[i] = 0;
}

__global__ void k_hist(const int* __restrict__ dst, int* __restrict__ cnt, int E) {
    int e = blockIdx.x * blockDim.x + threadIdx.x;
    if (e < E) atomicAdd(cnt + dst[e], 1);
}

#define SCAN_T 1024
__global__ void k_scan(const int* __restrict__ cnt, int* __restrict__ row_start,
                       int* __restrict__ cursor, float* __restrict__ dis, int n) {
    __shared__ int part[SCAN_T];
    int tid = threadIdx.x;
    int chunk = (n + SCAN_T - 1) / SCAN_T;
    int lo = tid * chunk;
    int hi = min(lo + chunk, n);
    int s = 0;
    for (int i = lo; i < hi; i++) s += cnt[i];
    part[tid] = s;
    __syncthreads();
    for (int off = 1; off < SCAN_T; off <<= 1) {
        int t = 0;
        if (tid >= off) t = part[tid - off];
        __syncthreads();
        if (tid >= off) part[tid] += t;
        __syncthreads();
    }
    int run = part[tid] - s;  // exclusive
    for (int i = lo; i < hi; i++) {
        int c = cnt[i];
        row_start[i] = run;
        cursor[i] = run;
        dis[i] = rsqrtf((float)(c + 1));  // degree incl. self-loop
        run += c;
    }
    if (tid == SCAN_T - 1) row_start[n] = run;
}

__global__ void k_bucket(const int* __restrict__ src, const int* __restrict__ dst,
                         int* __restrict__ cursor, int* __restrict__ esrc, int E) {
    int e = blockIdx.x * blockDim.x + threadIdx.x;
    if (e >= E) return;
    int pos = atomicAdd(cursor + dst[e], 1);
    esrc[pos] = src[e];
}

// ---------------- one-time W -> tf32 fragment-order conversion ----------------
__device__ __forceinline__ unsigned cvt_tf32(float f) {
    unsigned u;
    asm("cvt.rna.tf32.f32 %0, %1;" : "=r"(u) : "f"(f));
    return u;
}

// frag addr for W[k][n]: kt=k/8, nt=n/8, t=(n%8)*4+(k%4), slot=(k%8)/4
__global__ void k_wprep(const float* __restrict__ W, unsigned* __restrict__ Wf) {
    int idx = blockIdx.x * blockDim.x + threadIdx.x;  // 4096 float4
    if (idx >= 4096) return;
    int k = idx >> 5, n4 = idx & 31;
    float4 w = ((const float4*)W)[idx];
    int kt = k >> 3, kin = k & 7;
    int slot = kin >> 2, kk = kin & 3;
    float v[4] = {w.x, w.y, w.z, w.w};
#pragma unroll
    for (int j = 0; j < 4; j++) {
        int n = n4 * 4 + j;
        int nt = n >> 3, t = (n & 7) * 4 + kk;
        Wf[(((kt * 16) + nt) * 32 + t) * 2 + slot] = cvt_tf32(v[j]);
    }
}

// ---------------- tf32 tensor-core GEMM: hs[m] = (X[m] @ W) * dis[m] (fp16 out) --------
#define XLD 132
#define GEMM_SMEM (64 * XLD * 4 + 128 * 128 * 4)   // 33792 + 65536 = 99328 B

__global__ __launch_bounds__(128, 2) void k_gemm(
    const float* __restrict__ A,          // layer-1 input (or null)
    const float4* __restrict__ ACC,       // layer-2 fused input (or null)
    const unsigned* __restrict__ WfG,     // pre-converted fragment-order W
    const float* __restrict__ dis,
    const float* __restrict__ bias,
    __half2* __restrict__ hsh, int M) {
    extern __shared__ unsigned smem_u[];
    unsigned* Xs = smem_u;                     // [64][XLD] tf32 bits
    unsigned* Wf = smem_u + 64 * XLD;          // frag layout copy
    const int tid = threadIdx.x;
    const int warp = tid >> 5;
    const int lane = tid & 31;
    const int gid = lane >> 2;   // 0..7
    const int tig = lane & 3;    // 0..3
    const int m0 = blockIdx.x * 64;

    // Straight coalesced copy of fragment-order W (64KB)
    {
        const uint4* src4 = (const uint4*)WfG;
        uint4* dst4 = (uint4*)Wf;
#pragma unroll
        for (int i = 0; i < 32; i++) dst4[tid + i * 128] = src4[tid + i * 128];
    }
    // Load + convert X tile (64 rows x 32 float4)
    if (A != nullptr) {
#pragma unroll
        for (int i = 0; i < 16; i++) {
            int idx = tid + i * 128;
            int r = idx >> 5, c4 = idx & 31;
            int m = m0 + r;
            float4 v = make_float4(0.f, 0.f, 0.f, 0.f);
            if (m < M) v = ((const float4*)(A + (size_t)m * D))[c4];
            uint4 u = make_uint4(cvt_tf32(v.x), cvt_tf32(v.y), cvt_tf32(v.z), cvt_tf32(v.w));
            *(uint4*)(Xs + r * XLD + c4 * 4) = u;
        }
    } else {  // fused: x = relu(dis[m]*ACC[m] + bias)
#pragma unroll
        for (int i = 0; i < 16; i++) {
            int idx = tid + i * 128;
            int r = idx >> 5, c4 = idx & 31;
            int m = m0 + r;
            float4 v = make_float4(0.f, 0.f, 0.f, 0.f);
            if (m < M) {
                float s = dis[m];
                float4 a = ACC[(size_t)m * D4 + c4];
                float4 bb = ((const float4*)bias)[c4];
                v.x = fmaxf(a.x * s + bb.x, 0.f);
                v.y = fmaxf(a.y * s + bb.y, 0.f);
                v.z = fmaxf(a.z * s + bb.z, 0.f);
                v.w = fmaxf(a.w * s + bb.w, 0.f);
            }
            uint4 u = make_uint4(cvt_tf32(v.x), cvt_tf32(v.y), cvt_tf32(v.z), cvt_tf32(v.w));
            *(uint4*)(Xs + r * XLD + c4 * 4) = u;
        }
    }
    __syncthreads();

    const int mrow = warp * 16;
    float d[16][4];
#pragma unroll
    for (int nt = 0; nt < 16; nt++)
#pragma unroll
        for (int j = 0; j < 4; j++) d[nt][j] = 0.f;

#pragma unroll
    for (int kt = 0; kt < 16; kt++) {
        unsigned a0 = Xs[(mrow + gid) * XLD + kt * 8 + tig];
        unsigned a1 = Xs[(mrow + gid + 8) * XLD + kt * 8 + tig];
        unsigned a2 = Xs[(mrow + gid) * XLD + kt * 8 + tig + 4];
        unsigned a3 = Xs[(mrow + gid + 8) * XLD + kt * 8 + tig + 4];
#pragma unroll
        for (int nt = 0; nt < 16; nt++) {
            uint2 b = *(const uint2*)(Wf + (((kt * 16) + nt) * 32 + lane) * 2);
            asm volatile(
                "mma.sync.aligned.m16n8k8.row.col.f32.tf32.tf32.f32 "
                "{%0,%1,%2,%3}, {%4,%5,%6,%7}, {%8,%9}, {%0,%1,%2,%3};"
                : "+f"(d[nt][0]), "+f"(d[nt][1]), "+f"(d[nt][2]), "+f"(d[nt][3])
                : "r"(a0), "r"(a1), "r"(a2), "r"(a3), "r"(b.x), "r"(b.y));
        }
    }

    // Epilogue: c0=(gid,2tig) c1=(gid,2tig+1) c2=(gid+8,2tig) c3=(gid+8,2tig+1)
    int mA = m0 + mrow + gid;
    int mB = mA + 8;
    float sA = (mA < M) ? dis[mA] : 0.f;
    float sB = (mB < M) ? dis[mB] : 0.f;
#pragma unroll
    for (int nt = 0; nt < 16; nt++) {
        int col2 = nt * 4 + tig;   // half2 index within row (64 half2 per row)
        if (mA < M) hsh[(size_t)mA * 64 + col2] = __floats2half2_rn(d[nt][0] * sA, d[nt][1] * sA);
        if (mB < M) hsh[(size_t)mB * 64 + col2] = __floats2half2_rn(d[nt][2] * sB, d[nt][3] * sB);
    }
}

// ---------------- gather-reduce: out[n] = hs[n] + sum_{e in bucket(n)} hs[esrc[e]] ----------------
// One warp per node; fp16 rows (8B per lane), fp32 accumulation.
template <int FUSE>
__global__ void k_gather(const __half2* __restrict__ hsh,
                         const int* __restrict__ esrc,
                         const int* __restrict__ row_start,
                         const float* __restrict__ dis,
                         const float* __restrict__ bias,
                         float4* __restrict__ outp, int n) {
    int w = (blockIdx.x * blockDim.x + threadIdx.x) >> 5;
    if (w >= n) return;
    int lane = threadIdx.x & 31;
    const uint2* rows = (const uint2*)hsh;   // one uint2 = 4 halves = 4 cols

    uint2 u = rows[(size_t)w * 32 + lane];   // self-loop
    float2 p0 = __half22float2(*(const __half2*)&u.x);
    float2 p1 = __half22float2(*(const __half2*)&u.y);
    float ax = p0.x, ay = p0.y, az = p1.x, aw = p1.y;

    int i = row_start[w];
    int hi = row_start[w + 1];
    for (; i + 4 <= hi; i += 4) {
        int s0 = __ldg(esrc + i), s1 = __ldg(esrc + i + 1);
        int s2 = __ldg(esrc + i + 2), s3 = __ldg(esrc + i + 3);
        uint2 u0 = rows[(size_t)s0 * 32 + lane];
        uint2 u1 = rows[(size_t)s1 * 32 + lane];
        uint2 u2 = rows[(size_t)s2 * 32 + lane];
        uint2 u3 = rows[(size_t)s3 * 32 + lane];
        float2 q;
        q = __half22float2(*(const __half2*)&u0.x); ax += q.x; ay += q.y;
        q = __half22float2(*(const __half2*)&u0.y); az += q.x; aw += q.y;
        q = __half22float2(*(const __half2*)&u1.x); ax += q.x; ay += q.y;
        q = __half22float2(*(const __half2*)&u1.y); az += q.x; aw += q.y;
        q = __half22float2(*(const __half2*)&u2.x); ax += q.x; ay += q.y;
        q = __half22float2(*(const __half2*)&u2.y); az += q.x; aw += q.y;
        q = __half22float2(*(const __half2*)&u3.x); ax += q.x; ay += q.y;
        q = __half22float2(*(const __half2*)&u3.y); az += q.x; aw += q.y;
    }
    for (; i < hi; i++) {
        int s = __ldg(esrc + i);
        uint2 uu = rows[(size_t)s * 32 + lane];
        float2 q;
        q = __half22float2(*(const __half2*)&uu.x); ax += q.x; ay += q.y;
        q = __half22float2(*(const __half2*)&uu.y); az += q.x; aw += q.y;
    }
    float4 a = make_float4(ax, ay, az, aw);
    if (FUSE) {
        float sc = dis[w];
        float4 bb = ((const float4*)bias)[lane];
        a.x = fmaxf(a.x * sc + bb.x, 0.f);
        a.y = fmaxf(a.y * sc + bb.y, 0.f);
        a.z = fmaxf(a.z * sc + bb.z, 0.f);
        a.w = fmaxf(a.w * sc + bb.w, 0.f);
    }
    outp[(size_t)w * D4 + lane] = a;
}

extern "C" void kernel_launch(void* const* d_in, const int* in_sizes, int n_in,
                              void* d_out, int out_size) {
    const float* x   = (const float*)d_in[0];
    const int*   ei  = (const int*)d_in[1];   // int64 in reference -> delivered as int32
    const float* W1  = (const float*)d_in[2];
    const float* b1  = (const float*)d_in[3];
    const float* W2  = (const float*)d_in[4];
    const float* b2  = (const float*)d_in[5];
    float4* out = (float4*)d_out;

    int N = in_sizes[0] / D;
    int E = in_sizes[1] / 2;
    const int* src = ei;
    const int* dst = ei + E;

    float *dis;
    float4 *acc;
    __half2 *hsh;
    int *cnt, *row, *cur, *esrc;
    unsigned *wf1, *wf2;
    cudaGetSymbolAddress((void**)&dis, g_dis);
    cudaGetSymbolAddress((void**)&hsh, g_hsh);
    cudaGetSymbolAddress((void**)&acc, g_acc);
    cudaGetSymbolAddress((void**)&cnt, g_cnt);
    cudaGetSymbolAddress((void**)&row, g_row);
    cudaGetSymbolAddress((void**)&cur, g_cur);
    cudaGetSymbolAddress((void**)&esrc, g_esrc);
    cudaGetSymbolAddress((void**)&wf1, g_wf1);
    cudaGetSymbolAddress((void**)&wf2, g_wf2);

    cudaFuncSetAttribute(k_gemm, cudaFuncAttributeMaxDynamicSharedMemorySize, GEMM_SMEM);

    int nb = (N + 255) / 256;
    int eb = (E + 255) / 256;
    int gblocks = (N + 63) / 64;
    long long gw = (long long)N * 32;
    int gab = (int)((gw + 255) / 256);

    // one-time W fragment conversion + bucket build (also produces dis)
    k_wprep<<<16, 256>>>(W1, wf1);
    k_wprep<<<16, 256>>>(W2, wf2);
    k_zero<<<nb, 256>>>(cnt, N);
    k_hist<<<eb, 256>>>(dst, cnt, E);
    k_scan<<<1, SCAN_T>>>(cnt, row, cur, dis, N);
    k_bucket<<<eb, 256>>>(src, dst, cur, esrc, E);

    // layer 1
    k_gemm<<<gblocks, 128, GEMM_SMEM>>>(x, nullptr, wf1, dis, nullptr, hsh, N);
    k_gather<0><<<gab, 256>>>(hsh, esrc, row, dis, nullptr, acc, N);

    // layer 2 (GEMM input fused: relu(dis*acc + b1); gather output fused: relu(dis*a + b2))
    k_gemm<<<gblocks, 128, GEMM_SMEM>>>(nullptr, acc, wf2, dis, b1, hsh, N);
    k_gather<1><<<gab, 256>>>(hsh, esrc, row, dis, b2, out, N);
}